// round 4
// baseline (speedup 1.0000x reference)
#include <cuda_runtime.h>

#define N_SAMP 384
#define M 12
#define NP 6
#define UC (M * NP)      // 72 complex entries per sample

// g_u1[i][k][b] = U1_i[k][b] ; g_u2[j][k][a] = conj(U2_j[k][a])
__device__ float2 g_u1[N_SAMP * UC];
__device__ float2 g_u2[N_SAMP * UC];

__device__ __forceinline__ float2 cmul(float2 a, float2 b) {
    return make_float2(a.x * b.x - a.y * b.y, a.x * b.y + a.y * b.x);
}

// ---------------------------------------------------------------------------
// Stage 1 (single launch, grid=768): U(x) = A @ diag(exp(ix)) @ B, first NP cols.
// Blocks [0,384) -> x1 -> g_u1 ; blocks [384,768) -> x2 -> conj -> g_u2.
// ---------------------------------------------------------------------------
__global__ void build_u_kernel(const float* __restrict__ x1,
                               const float* __restrict__ x2,
                               const float* __restrict__ A_re,
                               const float* __restrict__ A_im,
                               const float* __restrict__ B_re,
                               const float* __restrict__ B_im)
{
    __shared__ float2 ph[M];
    __shared__ float2 sA[M * M];
    __shared__ float2 sB[M][NP];

    const int s      = blockIdx.x;
    const int tid    = threadIdx.x;
    const int second = (s >= N_SAMP);
    const int ss     = second ? s - N_SAMP : s;
    const float* x   = second ? x2 : x1;

    if (tid < M * M) sA[tid] = make_float2(A_re[tid], A_im[tid]);
    if (tid < M * NP) {
        int b = tid / NP, c = tid - b * NP;
        sB[b][c] = make_float2(B_re[b * M + c], B_im[b * M + c]);
    }
    if (tid < M) {
        float sn, cs;
        sincosf(x[ss * M + tid], &sn, &cs);
        ph[tid] = make_float2(cs, sn);
    }
    __syncthreads();

    if (tid < M * NP) {
        const int a = tid / NP;
        const int c = tid - a * NP;
        float2 acc = make_float2(0.f, 0.f);
#pragma unroll
        for (int b = 0; b < M; ++b) {
            float2 t  = cmul(ph[b], sB[b][c]);
            float2 Av = sA[a * M + b];
            acc.x += Av.x * t.x - Av.y * t.y;
            acc.y += Av.x * t.y + Av.y * t.x;
        }
        if (second) {
            acc.y = -acc.y;
            g_u2[ss * UC + tid] = acc;
        } else {
            g_u1[ss * UC + tid] = acc;
        }
    }
}

// ---------------------------------------------------------------------------
// Stage 2: per pair (i,j): W[a][b] = sum_k conjU2[j][k][a] * U1[i][k][b],
// then Glynn permanent via TWO independent Gray-code chains (delta5 = +/-1),
// K = |perm|^2. 16x16 pair tile per block.
// ---------------------------------------------------------------------------
#define SPITCH 73   // per-sample smem pitch (float2), kills bank conflicts

__device__ __forceinline__ float2 prod6(const float2* r) {
    float2 p01 = cmul(r[0], r[1]);
    float2 p23 = cmul(r[2], r[3]);
    float2 p45 = cmul(r[4], r[5]);
    return cmul(cmul(p01, p23), p45);
}

__global__ __launch_bounds__(256) void pair_kernel(float* __restrict__ out)
{
    __shared__ float2 s1[16 * SPITCH];
    __shared__ float2 s2[16 * SPITCH];

    const int i0  = blockIdx.y * 16;
    const int j0  = blockIdx.x * 16;
    const int tid = threadIdx.x;

    for (int e = tid; e < 16 * UC; e += 256) {
        int l = e / UC;
        int r = e - l * UC;
        s1[l * SPITCH + r] = g_u1[(i0 + l) * UC + r];
        s2[l * SPITCH + r] = g_u2[(j0 + l) * UC + r];
    }
    __syncthreads();

    const int lj = tid & 15;        // j fastest -> coalesced output
    const int li = tid >> 4;
    const float2* __restrict__ p1 = &s1[li * SPITCH];
    const float2* __restrict__ p2 = &s2[lj * SPITCH];

    float2 W[NP][NP];
#pragma unroll
    for (int a = 0; a < NP; ++a)
#pragma unroll
        for (int b = 0; b < NP; ++b)
            W[a][b] = make_float2(0.f, 0.f);

#pragma unroll
    for (int k = 0; k < M; ++k) {
        float2 a6[NP], b6[NP];
#pragma unroll
        for (int a = 0; a < NP; ++a) a6[a] = p2[k * NP + a];
#pragma unroll
        for (int b = 0; b < NP; ++b) b6[b] = p1[k * NP + b];
#pragma unroll
        for (int a = 0; a < NP; ++a)
#pragma unroll
            for (int b = 0; b < NP; ++b) {
                W[a][b].x += a6[a].x * b6[b].x - a6[a].y * b6[b].y;
                W[a][b].y += a6[a].x * b6[b].y + a6[a].y * b6[b].x;
            }
    }

    // --- Glynn permanent, n=6, dual Gray chains ---
    // Chain A: delta5 = +1 ; Chain B: delta5 = -1 (parity flipped vs A).
    // Both chains walk the same gray schedule over rows 1..4 (16 steps each).
    float2 rA[NP], rB[NP];
#pragma unroll
    for (int j = 0; j < NP; ++j) {
        float2 t = W[0][j];
#pragma unroll
        for (int a = 1; a < NP; ++a) {
            t.x += W[a][j].x;
            t.y += W[a][j].y;
        }
        rA[j] = t;
        rB[j] = make_float2(t.x - 2.f * W[5][j].x, t.y - 2.f * W[5][j].y);
    }

    float2 acc;
    {
        float2 pA = prod6(rA);
        float2 pB = prod6(rB);
        acc = make_float2(pA.x - pB.x, pA.y - pB.y);   // sg0 = +1 for A, -1 for B
    }

#pragma unroll
    for (int t = 1; t < 16; ++t) {
        const int bit = (t & 1) ? 0 : ((t & 2) ? 1 : ((t & 4) ? 2 : 3));
        const int a   = bit + 1;                              // flipped row (1..4)
        const float s2v = (((t ^ (t >> 1)) >> bit) & 1) ? -2.f : 2.f;
        const float sg  = (t & 1) ? -1.f : 1.f;               // parity of chain A

#pragma unroll
        for (int j = 0; j < NP; ++j) {
            rA[j].x += s2v * W[a][j].x;
            rA[j].y += s2v * W[a][j].y;
            rB[j].x += s2v * W[a][j].x;
            rB[j].y += s2v * W[a][j].y;
        }
        float2 pA = prod6(rA);
        float2 pB = prod6(rB);
        acc.x += sg * (pA.x - pB.x);
        acc.y += sg * (pA.y - pB.y);
    }

    // perm = acc / 32 ; K = |perm|^2 = |acc|^2 / 1024
    const float K = (acc.x * acc.x + acc.y * acc.y) * (1.0f / 1024.0f);
    out[(i0 + li) * N_SAMP + (j0 + lj)] = K;
}

// ---------------------------------------------------------------------------
extern "C" void kernel_launch(void* const* d_in, const int* in_sizes, int n_in,
                              void* d_out, int out_size)
{
    const float* x1   = (const float*)d_in[0];
    const float* x2   = (const float*)d_in[1];
    const float* A_re = (const float*)d_in[2];
    const float* A_im = (const float*)d_in[3];
    const float* B_re = (const float*)d_in[4];
    const float* B_im = (const float*)d_in[5];

    build_u_kernel<<<2 * N_SAMP, 160>>>(x1, x2, A_re, A_im, B_re, B_im);

    dim3 grid(N_SAMP / 16, N_SAMP / 16);   // 24 x 24
    pair_kernel<<<grid, 256>>>((float*)d_out);
}